// round 1
// baseline (speedup 1.0000x reference)
#include <cuda_runtime.h>
#include <math.h>

// ============================================================================
// FullyConnectedSteerableGeometricProductLayer — Cl(3,0) geometric algebra
//   B=1024, N_IN=N_OUT=256, DIM_MV=8, N_PATHS=20
// Decomposition:
//   xr   = normalize(mv_linear(x, w_right))           -> 8 grade-shared GEMMs
//   u    = per-(b,n) bilinear Cayley contraction       -> elementwise kernel
//   prod = grouped GEMM over (n, path) per grade       -> 4 GEMMs
//   left = mv_linear(x, w_left) + bias                 -> 8 grade-shared GEMMs
//   out  = (left + prod) / sqrt(2)
// ============================================================================

#define QP  (1024 * 256)     // plane size [b][chan]
#define RSQRT2 0.70710678118654752440f

// ---------------- device scratch (static; no allocations) -------------------
__device__ float g_xt  [8 * QP];        // x transposed: [comp][b][m]
__device__ float g_xr  [8 * QP];        // x_right (raw) planes: [comp][b][n]
__device__ float g_left[8 * QP];        // left linear planes: [comp][b][mo]
__device__ float g_prod[8 * QP];        // prod planes: [comp][b][mo]
__device__ float g_wrt [4 * 256 * 256]; // w_right per-grade: [g][n][m]
__device__ float g_wlt [4 * 256 * 256]; // w_left  per-grade: [g][n][m]
__device__ float g_wg  [1310720];       // grouped gp weights: per grade [mo][(n,p)]
__device__ float g_U   [11534336];      // grouped U: per grade [(jl,b)][(n,p)]

// ---------------- compile-time GA tables (Cl(3,0), blade order 0,1,2,4,3,5,6,7)
#define GA_TABLES \
  constexpr int   T_GR[8]     = {0,1,1,1,2,2,2,3};                       \
  constexpr int   T_RES[8][8] = {                                        \
    {0,1,2,3,4,5,6,7},                                                   \
    {1,0,4,5,2,3,7,6},                                                   \
    {2,4,0,6,1,7,3,5},                                                   \
    {3,5,6,0,7,1,2,4},                                                   \
    {4,2,1,7,0,6,5,3},                                                   \
    {5,3,7,1,6,0,4,2},                                                   \
    {6,7,3,2,5,4,0,1},                                                   \
    {7,6,5,4,3,2,1,0}};                                                  \
  constexpr float T_SGN[8][8] = {                                        \
    { 1.f, 1.f, 1.f, 1.f, 1.f, 1.f, 1.f, 1.f},                           \
    { 1.f, 1.f, 1.f, 1.f, 1.f, 1.f, 1.f, 1.f},                           \
    { 1.f,-1.f, 1.f, 1.f,-1.f,-1.f, 1.f,-1.f},                           \
    { 1.f,-1.f,-1.f, 1.f, 1.f,-1.f,-1.f, 1.f},                           \
    { 1.f,-1.f, 1.f, 1.f,-1.f,-1.f, 1.f,-1.f},                           \
    { 1.f,-1.f,-1.f, 1.f, 1.f,-1.f,-1.f, 1.f},                           \
    { 1.f, 1.f,-1.f, 1.f,-1.f, 1.f,-1.f,-1.f},                           \
    { 1.f, 1.f,-1.f, 1.f,-1.f, 1.f,-1.f,-1.f}};                          \
  constexpr int   T_PLOC[4][4][4] = {                                    \
    { { 0,-1,-1,-1},{-1, 0,-1,-1},{-1,-1, 0,-1},{-1,-1,-1, 0} },         \
    { {-1, 1,-1,-1},{ 1,-1, 2,-1},{-1, 1,-1, 2},{-1,-1, 1,-1} },         \
    { {-1,-1, 2,-1},{-1, 3,-1, 4},{ 3,-1, 4,-1},{-1, 2,-1,-1} },         \
    { {-1,-1,-1, 3},{-1,-1, 5,-1},{-1, 5,-1,-1},{ 3,-1,-1,-1} } };       \
  constexpr int   T_NP[4]    = {4,6,6,4};                                \
  constexpr int   T_JLOC[8]  = {0,0,1,2,0,1,2,0};                        \
  constexpr int   T_JBASE[4] = {0,1,4,7};                                \
  constexpr long  T_UOFF[4]  = {0L, 1048576L, 5767168L, 10485760L};      \
  constexpr long  T_WOFF[4]  = {0L,  262144L,  655360L,  1048576L};      \
  constexpr int   T_GLOBALP[4][6] = {                                    \
    {0,4,10,16,0,0},{1,5,6,11,12,17},{2,7,8,13,14,18},{3,9,15,19,0,0} };

// ---------------- prep kernels ----------------------------------------------
__global__ void k_transpose_x(const float* __restrict__ x)
{
    int t = blockIdx.x * 256 + threadIdx.x;       // t = b*256 + m
    const float4* xp = reinterpret_cast<const float4*>(x + (size_t)t * 8);
    float4 v0 = xp[0], v1 = xp[1];
    g_xt[0 * QP + t] = v0.x; g_xt[1 * QP + t] = v0.y;
    g_xt[2 * QP + t] = v0.z; g_xt[3 * QP + t] = v0.w;
    g_xt[4 * QP + t] = v1.x; g_xt[5 * QP + t] = v1.y;
    g_xt[6 * QP + t] = v1.z; g_xt[7 * QP + t] = v1.w;
}

__global__ void k_prep_w(const float* __restrict__ wr, const float* __restrict__ wl)
{
    int t = blockIdx.x * 256 + threadIdx.x;       // t = n*256 + m
    float4 a = reinterpret_cast<const float4*>(wr)[t];
    g_wrt[0 * 65536 + t] = a.x; g_wrt[1 * 65536 + t] = a.y;
    g_wrt[2 * 65536 + t] = a.z; g_wrt[3 * 65536 + t] = a.w;
    float4 c = reinterpret_cast<const float4*>(wl)[t];
    g_wlt[0 * 65536 + t] = c.x; g_wlt[1 * 65536 + t] = c.y;
    g_wlt[2 * 65536 + t] = c.z; g_wlt[3 * 65536 + t] = c.w;
}

__global__ void k_prep_gpw(const float* __restrict__ gpw)
{
    GA_TABLES
    int t  = blockIdx.x * 256 + threadIdx.x;      // t = mo*256 + n
    int mo = t >> 8, n = t & 255;
    float w[20];
    const float4* p4 = reinterpret_cast<const float4*>(gpw + (size_t)t * 20);
    #pragma unroll
    for (int q = 0; q < 5; ++q) {
        float4 v = p4[q];
        w[q * 4 + 0] = v.x; w[q * 4 + 1] = v.y; w[q * 4 + 2] = v.z; w[q * 4 + 3] = v.w;
    }
    #pragma unroll
    for (int g = 0; g < 4; ++g) {
        int np = T_NP[g];
        long base = T_WOFF[g] + (long)mo * (256L * np) + (long)n * np;
        #pragma unroll
        for (int pl = 0; pl < 6; ++pl)
            if (pl < np) g_wg[base + pl] = w[T_GLOBALP[g][pl]];
    }
}

// ---------------- tiled SGEMM core: C[r,c] = sum_k A[r,k]*B[c,k] ------------
#define SG_BM 128
#define SG_BN 64
#define SG_BK 16

__device__ __forceinline__ void sgemm_core(
    const float* __restrict__ A,   // block-row base, row-major, lda = K
    const float* __restrict__ B,   // block-col base, row-major, ldb = K
    int K, float acc[8][4])
{
    __shared__ float As[SG_BK][SG_BM + 4];
    __shared__ float Bs[SG_BK][SG_BN + 4];
    const int tid = threadIdx.x;
    const int tx  = tid & 15;
    const int ty  = tid >> 4;

    for (int kt = 0; kt < K; kt += SG_BK) {
        #pragma unroll
        for (int it = 0; it < 2; ++it) {          // A tile: 128x16 = 512 float4
            int v   = tid + it * 256;
            int row = v >> 2;
            int kq  = (v & 3) << 2;
            float4 a4 = *reinterpret_cast<const float4*>(A + (size_t)row * K + kt + kq);
            As[kq + 0][row] = a4.x; As[kq + 1][row] = a4.y;
            As[kq + 2][row] = a4.z; As[kq + 3][row] = a4.w;
        }
        {                                          // B tile: 64x16 = 256 float4
            int col = tid >> 2;
            int kq  = (tid & 3) << 2;
            float4 b4 = *reinterpret_cast<const float4*>(B + (size_t)col * K + kt + kq);
            Bs[kq + 0][col] = b4.x; Bs[kq + 1][col] = b4.y;
            Bs[kq + 2][col] = b4.z; Bs[kq + 3][col] = b4.w;
        }
        __syncthreads();
        #pragma unroll
        for (int kk = 0; kk < SG_BK; ++kk) {
            float4 a0 = *reinterpret_cast<const float4*>(&As[kk][ty * 8]);
            float4 a1 = *reinterpret_cast<const float4*>(&As[kk][ty * 8 + 4]);
            float4 b0 = *reinterpret_cast<const float4*>(&Bs[kk][tx * 4]);
            float av[8] = {a0.x, a0.y, a0.z, a0.w, a1.x, a1.y, a1.z, a1.w};
            float bv[4] = {b0.x, b0.y, b0.z, b0.w};
            #pragma unroll
            for (int ii = 0; ii < 8; ++ii)
                #pragma unroll
                for (int jj = 0; jj < 4; ++jj)
                    acc[ii][jj] += av[ii] * bv[jj];
        }
        __syncthreads();
    }
}

// ---------------- component-wise linears (right which=0, left which=1) ------
__global__ void k_sgemm8(int /*unused*/)
{
    GA_TABLES
    int z     = blockIdx.z & 7;
    int which = blockIdx.z >> 3;
    const float* A = g_xt + (size_t)z * QP + (size_t)blockIdx.y * SG_BM * 256;
    const float* Bbase = which ? g_wlt : g_wrt;
    const float* B = Bbase + (size_t)T_GR[z] * 65536 + (size_t)blockIdx.x * SG_BN * 256;
    float acc[8][4];
    #pragma unroll
    for (int i = 0; i < 8; ++i)
        #pragma unroll
        for (int j = 0; j < 4; ++j) acc[i][j] = 0.f;
    sgemm_core(A, B, 256, acc);

    int tx = threadIdx.x & 15, ty = threadIdx.x >> 4;
    float* Cbase = which ? g_left : g_xr;
    float* C = Cbase + (size_t)z * QP
             + ((size_t)blockIdx.y * SG_BM + ty * 8) * 256
             + blockIdx.x * SG_BN + tx * 4;
    #pragma unroll
    for (int ii = 0; ii < 8; ++ii)
        *reinterpret_cast<float4*>(C + (size_t)ii * 256) =
            make_float4(acc[ii][0], acc[ii][1], acc[ii][2], acc[ii][3]);
}

// ---------------- normalize x_right + build grouped U -----------------------
__global__ void k_build_U(const float* __restrict__ x, const float* __restrict__ norm_a)
{
    GA_TABLES
    int t = blockIdx.x * 256 + threadIdx.x;       // t = b*256 + n
    int n = t & 255;
    int b = t >> 8;

    float xv[8];
    {
        const float4* xp = reinterpret_cast<const float4*>(x + (size_t)t * 8);
        float4 v0 = xp[0], v1 = xp[1];
        xv[0]=v0.x; xv[1]=v0.y; xv[2]=v0.z; xv[3]=v0.w;
        xv[4]=v1.x; xv[5]=v1.y; xv[6]=v1.z; xv[7]=v1.w;
    }
    float xr[8];
    #pragma unroll
    for (int i = 0; i < 8; ++i) xr[i] = g_xr[i * QP + t];

    float ngr[4];
    ngr[0] = sqrtf(xr[0]*xr[0]);
    ngr[1] = sqrtf(xr[1]*xr[1] + xr[2]*xr[2] + xr[3]*xr[3]);
    ngr[2] = sqrtf(xr[4]*xr[4] + xr[5]*xr[5] + xr[6]*xr[6]);
    ngr[3] = sqrtf(xr[7]*xr[7]);
    float inv[4];
    #pragma unroll
    for (int g = 0; g < 4; ++g) {
        float a   = norm_a[n * 4 + g];
        float sig = 1.f / (1.f + expf(-a));
        inv[g] = 1.f / (sig * (ngr[g] - 1.f) + 1.f + 1e-6f);
    }
    #pragma unroll
    for (int i = 0; i < 8; ++i) xr[i] *= inv[T_GR[i]];

    float u[8][6];
    #pragma unroll
    for (int a = 0; a < 8; ++a)
        #pragma unroll
        for (int p = 0; p < 6; ++p) u[a][p] = 0.f;

    #pragma unroll
    for (int i = 0; i < 8; ++i) {
        #pragma unroll
        for (int k = 0; k < 8; ++k) {
            int jc = T_RES[i][k];
            int pl = T_PLOC[T_GR[i]][T_GR[jc]][T_GR[k]];
            u[jc][pl] += T_SGN[i][k] * xv[i] * xr[k];
        }
    }

    #pragma unroll
    for (int jc = 0; jc < 8; ++jc) {
        int g  = T_GR[jc];
        int np = T_NP[g];
        long base = T_UOFF[g]
                  + (long)(T_JLOC[jc] * 1024 + b) * (256L * np)
                  + (long)n * np;
        #pragma unroll
        for (int p = 0; p < 6; ++p)
            if (p < np) g_U[base + p] = u[jc][p];
    }
}

// ---------------- grouped path GEMMs (all 4 grades, one launch) -------------
__global__ void k_sgemm_groups()
{
    GA_TABLES
    int y = blockIdx.y;
    int g, ly;
    if      (y <  8) { g = 0; ly = y;      }
    else if (y < 32) { g = 1; ly = y -  8; }
    else if (y < 56) { g = 2; ly = y - 32; }
    else             { g = 3; ly = y - 56; }
    int K = 256 * T_NP[g];
    const float* A = g_U  + T_UOFF[g] + (size_t)ly        * SG_BM * K;
    const float* B = g_wg + T_WOFF[g] + (size_t)blockIdx.x * SG_BN * K;
    float acc[8][4];
    #pragma unroll
    for (int i = 0; i < 8; ++i)
        #pragma unroll
        for (int j = 0; j < 4; ++j) acc[i][j] = 0.f;
    sgemm_core(A, B, K, acc);

    int tx = threadIdx.x & 15, ty = threadIdx.x >> 4;
    int r0 = ly * SG_BM + ty * 8;
    int c0 = blockIdx.x * SG_BN + tx * 4;
    #pragma unroll
    for (int ii = 0; ii < 8; ++ii) {
        int r  = r0 + ii;
        int jc = T_JBASE[g] + (r >> 10);
        int bb = r & 1023;
        *reinterpret_cast<float4*>(&g_prod[(size_t)jc * QP + (size_t)bb * 256 + c0]) =
            make_float4(acc[ii][0], acc[ii][1], acc[ii][2], acc[ii][3]);
    }
}

// ---------------- final combine ---------------------------------------------
__global__ void k_combine(const float* __restrict__ b_left, float* __restrict__ out)
{
    int t = blockIdx.x * 256 + threadIdx.x;       // t = b*256 + mo
    int m = t & 255;
    float o[8];
    #pragma unroll
    for (int j = 0; j < 8; ++j) {
        float v = g_left[j * QP + t] + g_prod[j * QP + t];
        if (j == 0) v += b_left[m];
        o[j] = v * RSQRT2;
    }
    float4* op = reinterpret_cast<float4*>(out + (size_t)t * 8);
    op[0] = make_float4(o[0], o[1], o[2], o[3]);
    op[1] = make_float4(o[4], o[5], o[6], o[7]);
}

// ---------------- launch ----------------------------------------------------
extern "C" void kernel_launch(void* const* d_in, const int* in_sizes, int n_in,
                              void* d_out, int out_size)
{
    const float* x   = (const float*)d_in[0];
    const float* wr  = (const float*)d_in[1];
    const float* wl  = (const float*)d_in[2];
    const float* bl  = (const float*)d_in[3];
    const float* na  = (const float*)d_in[4];
    const float* gpw = (const float*)d_in[5];
    float* out = (float*)d_out;

    k_transpose_x<<<1024, 256>>>(x);
    k_prep_w<<<256, 256>>>(wr, wl);
    k_prep_gpw<<<256, 256>>>(gpw);

    // right + left linears in one launch: z in [0,16), z>>3 selects side
    k_sgemm8<<<dim3(4, 8, 16), 256>>>(0);

    k_build_U<<<1024, 256>>>(x, na);

    // grouped path GEMMs: grid.y = 8 + 24 + 24 + 8 = 64 block-rows
    k_sgemm_groups<<<dim3(4, 64), 256>>>();

    k_combine<<<1024, 256>>>(bl, out);
}

// round 2
// speedup vs baseline: 1.0640x; 1.0640x over previous
#include <cuda_runtime.h>
#include <math.h>

// ============================================================================
// FullyConnectedSteerableGeometricProductLayer — Cl(3,0) geometric algebra
//   B=1024, N_IN=N_OUT=256, DIM_MV=8, N_PATHS=20
// R2: 128x128x16 double-buffered SGEMM core (8x8 microtile, 256 thr, 2 CTA/SM)
// ============================================================================

#define QP  (1024 * 256)     // plane size [b][chan]
#define RSQRT2 0.70710678118654752440f

// ---------------- device scratch (static; no allocations) -------------------
__device__ float g_xt  [8 * QP];        // x transposed: [comp][b][m]
__device__ float g_xr  [8 * QP];        // x_right (raw) planes: [comp][b][n]
__device__ float g_left[8 * QP];        // left linear planes: [comp][b][mo]
__device__ float g_prod[8 * QP];        // prod planes: [comp][b][mo]
__device__ float g_wrt [4 * 256 * 256]; // w_right per-grade: [g][n][m]
__device__ float g_wlt [4 * 256 * 256]; // w_left  per-grade: [g][n][m]
__device__ float g_wg  [1310720];       // grouped gp weights: per grade [mo][(n,p)]
__device__ float g_U   [11534336];      // grouped U: per grade [(jl,b)][(n,p)]

// ---------------- compile-time GA tables (Cl(3,0), blade order 0,1,2,4,3,5,6,7)
#define GA_TABLES \
  constexpr int   T_GR[8]     = {0,1,1,1,2,2,2,3};                       \
  constexpr int   T_RES[8][8] = {                                        \
    {0,1,2,3,4,5,6,7},                                                   \
    {1,0,4,5,2,3,7,6},                                                   \
    {2,4,0,6,1,7,3,5},                                                   \
    {3,5,6,0,7,1,2,4},                                                   \
    {4,2,1,7,0,6,5,3},                                                   \
    {5,3,7,1,6,0,4,2},                                                   \
    {6,7,3,2,5,4,0,1},                                                   \
    {7,6,5,4,3,2,1,0}};                                                  \
  constexpr float T_SGN[8][8] = {                                        \
    { 1.f, 1.f, 1.f, 1.f, 1.f, 1.f, 1.f, 1.f},                           \
    { 1.f, 1.f, 1.f, 1.f, 1.f, 1.f, 1.f, 1.f},                           \
    { 1.f,-1.f, 1.f, 1.f,-1.f,-1.f, 1.f,-1.f},                           \
    { 1.f,-1.f,-1.f, 1.f, 1.f,-1.f,-1.f, 1.f},                           \
    { 1.f,-1.f, 1.f, 1.f,-1.f,-1.f, 1.f,-1.f},                           \
    { 1.f,-1.f,-1.f, 1.f, 1.f,-1.f,-1.f, 1.f},                           \
    { 1.f, 1.f,-1.f, 1.f,-1.f, 1.f,-1.f,-1.f},                           \
    { 1.f, 1.f,-1.f, 1.f,-1.f, 1.f,-1.f,-1.f}};                          \
  constexpr int   T_PLOC[4][4][4] = {                                    \
    { { 0,-1,-1,-1},{-1, 0,-1,-1},{-1,-1, 0,-1},{-1,-1,-1, 0} },         \
    { {-1, 1,-1,-1},{ 1,-1, 2,-1},{-1, 1,-1, 2},{-1,-1, 1,-1} },         \
    { {-1,-1, 2,-1},{-1, 3,-1, 4},{ 3,-1, 4,-1},{-1, 2,-1,-1} },         \
    { {-1,-1,-1, 3},{-1,-1, 5,-1},{-1, 5,-1,-1},{ 3,-1,-1,-1} } };       \
  constexpr int   T_NP[4]    = {4,6,6,4};                                \
  constexpr int   T_JLOC[8]  = {0,0,1,2,0,1,2,0};                        \
  constexpr int   T_JBASE[4] = {0,1,4,7};                                \
  constexpr long  T_UOFF[4]  = {0L, 1048576L, 5767168L, 10485760L};      \
  constexpr long  T_WOFF[4]  = {0L,  262144L,  655360L,  1048576L};      \
  constexpr int   T_GLOBALP[4][6] = {                                    \
    {0,4,10,16,0,0},{1,5,6,11,12,17},{2,7,8,13,14,18},{3,9,15,19,0,0} };

// ---------------- prep kernels ----------------------------------------------
__global__ void k_transpose_x(const float* __restrict__ x)
{
    int t = blockIdx.x * 256 + threadIdx.x;       // t = b*256 + m
    const float4* xp = reinterpret_cast<const float4*>(x + (size_t)t * 8);
    float4 v0 = xp[0], v1 = xp[1];
    g_xt[0 * QP + t] = v0.x; g_xt[1 * QP + t] = v0.y;
    g_xt[2 * QP + t] = v0.z; g_xt[3 * QP + t] = v0.w;
    g_xt[4 * QP + t] = v1.x; g_xt[5 * QP + t] = v1.y;
    g_xt[6 * QP + t] = v1.z; g_xt[7 * QP + t] = v1.w;
}

__global__ void k_prep_w(const float* __restrict__ wr, const float* __restrict__ wl)
{
    int t = blockIdx.x * 256 + threadIdx.x;       // t = n*256 + m
    float4 a = reinterpret_cast<const float4*>(wr)[t];
    g_wrt[0 * 65536 + t] = a.x; g_wrt[1 * 65536 + t] = a.y;
    g_wrt[2 * 65536 + t] = a.z; g_wrt[3 * 65536 + t] = a.w;
    float4 c = reinterpret_cast<const float4*>(wl)[t];
    g_wlt[0 * 65536 + t] = c.x; g_wlt[1 * 65536 + t] = c.y;
    g_wlt[2 * 65536 + t] = c.z; g_wlt[3 * 65536 + t] = c.w;
}

__global__ void k_prep_gpw(const float* __restrict__ gpw)
{
    GA_TABLES
    int t  = blockIdx.x * 256 + threadIdx.x;      // t = mo*256 + n
    int mo = t >> 8, n = t & 255;
    float w[20];
    const float4* p4 = reinterpret_cast<const float4*>(gpw + (size_t)t * 20);
    #pragma unroll
    for (int q = 0; q < 5; ++q) {
        float4 v = p4[q];
        w[q * 4 + 0] = v.x; w[q * 4 + 1] = v.y; w[q * 4 + 2] = v.z; w[q * 4 + 3] = v.w;
    }
    #pragma unroll
    for (int g = 0; g < 4; ++g) {
        int np = T_NP[g];
        long base = T_WOFF[g] + (long)mo * (256L * np) + (long)n * np;
        #pragma unroll
        for (int pl = 0; pl < 6; ++pl)
            if (pl < np) g_wg[base + pl] = w[T_GLOBALP[g][pl]];
    }
}

// ---------------- 128x128x16 double-buffered SGEMM core ---------------------
// C[r,c] = sum_k A[r,k]*B[c,k]; A,B row-major with ld = K (K % 16 == 0).
#define BM 128
#define BN 128
#define BK 16
#define SMS 132   // smem row stride (floats): 16B-aligned, conflict-free stores

__device__ __forceinline__ void sgemm128(
    const float* __restrict__ A, const float* __restrict__ B, int K,
    float acc[8][8])
{
    __shared__ float As[2][BK][SMS];
    __shared__ float Bs[2][BK][SMS];
    const int tid = threadIdx.x;
    const int lrow = tid & 127;          // smem tile row this thread loads
    const int lkq  = (tid >> 7) << 3;    // k-offset within tile: 0 or 8
    const int tx = tid & 15;             // col group
    const int ty = tid >> 4;             // row group

    #pragma unroll
    for (int i = 0; i < 8; ++i)
        #pragma unroll
        for (int j = 0; j < 8; ++j) acc[i][j] = 0.f;

    // prologue: load tile 0
    {
        const float* Ap = A + (size_t)lrow * K + lkq;
        const float* Bp = B + (size_t)lrow * K + lkq;
        float4 a0 = *(const float4*)Ap, a1 = *(const float4*)(Ap + 4);
        float4 b0 = *(const float4*)Bp, b1 = *(const float4*)(Bp + 4);
        As[0][lkq+0][lrow]=a0.x; As[0][lkq+1][lrow]=a0.y;
        As[0][lkq+2][lrow]=a0.z; As[0][lkq+3][lrow]=a0.w;
        As[0][lkq+4][lrow]=a1.x; As[0][lkq+5][lrow]=a1.y;
        As[0][lkq+6][lrow]=a1.z; As[0][lkq+7][lrow]=a1.w;
        Bs[0][lkq+0][lrow]=b0.x; Bs[0][lkq+1][lrow]=b0.y;
        Bs[0][lkq+2][lrow]=b0.z; Bs[0][lkq+3][lrow]=b0.w;
        Bs[0][lkq+4][lrow]=b1.x; Bs[0][lkq+5][lrow]=b1.y;
        Bs[0][lkq+6][lrow]=b1.z; Bs[0][lkq+7][lrow]=b1.w;
    }
    __syncthreads();

    int s = 0;
    for (int kt = 0; kt < K; kt += BK) {
        const int ktn = kt + BK;
        float4 pa0, pa1, pb0, pb1;
        if (ktn < K) {
            const float* Ap = A + (size_t)lrow * K + ktn + lkq;
            const float* Bp = B + (size_t)lrow * K + ktn + lkq;
            pa0 = *(const float4*)Ap; pa1 = *(const float4*)(Ap + 4);
            pb0 = *(const float4*)Bp; pb1 = *(const float4*)(Bp + 4);
        }
        #pragma unroll
        for (int kk = 0; kk < BK; ++kk) {
            float4 a0 = *(const float4*)&As[s][kk][ty * 8];
            float4 a1 = *(const float4*)&As[s][kk][ty * 8 + 4];
            float4 b0 = *(const float4*)&Bs[s][kk][tx * 4];
            float4 b1 = *(const float4*)&Bs[s][kk][64 + tx * 4];
            float av[8] = {a0.x,a0.y,a0.z,a0.w,a1.x,a1.y,a1.z,a1.w};
            float bv[8] = {b0.x,b0.y,b0.z,b0.w,b1.x,b1.y,b1.z,b1.w};
            #pragma unroll
            for (int ii = 0; ii < 8; ++ii)
                #pragma unroll
                for (int jj = 0; jj < 8; ++jj)
                    acc[ii][jj] += av[ii] * bv[jj];
        }
        if (ktn < K) {
            int ns = s ^ 1;
            As[ns][lkq+0][lrow]=pa0.x; As[ns][lkq+1][lrow]=pa0.y;
            As[ns][lkq+2][lrow]=pa0.z; As[ns][lkq+3][lrow]=pa0.w;
            As[ns][lkq+4][lrow]=pa1.x; As[ns][lkq+5][lrow]=pa1.y;
            As[ns][lkq+6][lrow]=pa1.z; As[ns][lkq+7][lrow]=pa1.w;
            Bs[ns][lkq+0][lrow]=pb0.x; Bs[ns][lkq+1][lrow]=pb0.y;
            Bs[ns][lkq+2][lrow]=pb0.z; Bs[ns][lkq+3][lrow]=pb0.w;
            Bs[ns][lkq+4][lrow]=pb1.x; Bs[ns][lkq+5][lrow]=pb1.y;
            Bs[ns][lkq+6][lrow]=pb1.z; Bs[ns][lkq+7][lrow]=pb1.w;
            __syncthreads();
            s = ns;
        }
    }
}

// ---------------- component-wise linears (right which=0, left which=1) ------
__global__ void __launch_bounds__(256, 2) k_sgemm8(int /*unused*/)
{
    GA_TABLES
    int z     = blockIdx.z & 7;
    int which = blockIdx.z >> 3;
    const float* A = g_xt + (size_t)z * QP + (size_t)blockIdx.y * BM * 256;
    const float* Bbase = which ? g_wlt : g_wrt;
    const float* B = Bbase + (size_t)T_GR[z] * 65536 + (size_t)blockIdx.x * BN * 256;
    float acc[8][8];
    sgemm128(A, B, 256, acc);

    int tx = threadIdx.x & 15, ty = threadIdx.x >> 4;
    float* Cbase = which ? g_left : g_xr;
    float* C = Cbase + (size_t)z * QP
             + ((size_t)blockIdx.y * BM + ty * 8) * 256
             + blockIdx.x * BN;
    #pragma unroll
    for (int ii = 0; ii < 8; ++ii) {
        *reinterpret_cast<float4*>(C + (size_t)ii * 256 + tx * 4) =
            make_float4(acc[ii][0], acc[ii][1], acc[ii][2], acc[ii][3]);
        *reinterpret_cast<float4*>(C + (size_t)ii * 256 + 64 + tx * 4) =
            make_float4(acc[ii][4], acc[ii][5], acc[ii][6], acc[ii][7]);
    }
}

// ---------------- normalize x_right + build grouped U -----------------------
__global__ void k_build_U(const float* __restrict__ x, const float* __restrict__ norm_a)
{
    GA_TABLES
    int t = blockIdx.x * 256 + threadIdx.x;       // t = b*256 + n
    int n = t & 255;
    int b = t >> 8;

    float xv[8];
    {
        const float4* xp = reinterpret_cast<const float4*>(x + (size_t)t * 8);
        float4 v0 = xp[0], v1 = xp[1];
        xv[0]=v0.x; xv[1]=v0.y; xv[2]=v0.z; xv[3]=v0.w;
        xv[4]=v1.x; xv[5]=v1.y; xv[6]=v1.z; xv[7]=v1.w;
    }
    float xr[8];
    #pragma unroll
    for (int i = 0; i < 8; ++i) xr[i] = g_xr[i * QP + t];

    float ngr[4];
    ngr[0] = sqrtf(xr[0]*xr[0]);
    ngr[1] = sqrtf(xr[1]*xr[1] + xr[2]*xr[2] + xr[3]*xr[3]);
    ngr[2] = sqrtf(xr[4]*xr[4] + xr[5]*xr[5] + xr[6]*xr[6]);
    ngr[3] = sqrtf(xr[7]*xr[7]);
    float inv[4];
    #pragma unroll
    for (int g = 0; g < 4; ++g) {
        float a   = norm_a[n * 4 + g];
        float sig = 1.f / (1.f + expf(-a));
        inv[g] = 1.f / (sig * (ngr[g] - 1.f) + 1.f + 1e-6f);
    }
    #pragma unroll
    for (int i = 0; i < 8; ++i) xr[i] *= inv[T_GR[i]];

    float u[8][6];
    #pragma unroll
    for (int a = 0; a < 8; ++a)
        #pragma unroll
        for (int p = 0; p < 6; ++p) u[a][p] = 0.f;

    #pragma unroll
    for (int i = 0; i < 8; ++i) {
        #pragma unroll
        for (int k = 0; k < 8; ++k) {
            int jc = T_RES[i][k];
            int pl = T_PLOC[T_GR[i]][T_GR[jc]][T_GR[k]];
            u[jc][pl] += T_SGN[i][k] * xv[i] * xr[k];
        }
    }

    #pragma unroll
    for (int jc = 0; jc < 8; ++jc) {
        int g  = T_GR[jc];
        int np = T_NP[g];
        long base = T_UOFF[g]
                  + (long)(T_JLOC[jc] * 1024 + b) * (256L * np)
                  + (long)n * np;
        #pragma unroll
        for (int p = 0; p < 6; ++p)
            if (p < np) g_U[base + p] = u[jc][p];
    }
}

// ---------------- grouped path GEMMs (all 4 grades, one launch) -------------
__global__ void __launch_bounds__(256, 2) k_sgemm_groups()
{
    GA_TABLES
    int y = blockIdx.y;
    int g, ly;
    if      (y <  8) { g = 0; ly = y;      }
    else if (y < 32) { g = 1; ly = y -  8; }
    else if (y < 56) { g = 2; ly = y - 32; }
    else             { g = 3; ly = y - 56; }
    int K = 256 * T_NP[g];
    const float* A = g_U  + T_UOFF[g] + (size_t)ly         * BM * K;
    const float* B = g_wg + T_WOFF[g] + (size_t)blockIdx.x * BN * K;
    float acc[8][8];
    sgemm128(A, B, K, acc);

    int tx = threadIdx.x & 15, ty = threadIdx.x >> 4;
    int r0 = ly * BM + ty * 8;
    int c0 = blockIdx.x * BN;
    #pragma unroll
    for (int ii = 0; ii < 8; ++ii) {
        int r  = r0 + ii;
        int jc = T_JBASE[g] + (r >> 10);
        int bb = r & 1023;
        float* Crow = &g_prod[(size_t)jc * QP + (size_t)bb * 256 + c0];
        *reinterpret_cast<float4*>(Crow + tx * 4) =
            make_float4(acc[ii][0], acc[ii][1], acc[ii][2], acc[ii][3]);
        *reinterpret_cast<float4*>(Crow + 64 + tx * 4) =
            make_float4(acc[ii][4], acc[ii][5], acc[ii][6], acc[ii][7]);
    }
}

// ---------------- final combine ---------------------------------------------
__global__ void k_combine(const float* __restrict__ b_left, float* __restrict__ out)
{
    int t = blockIdx.x * 256 + threadIdx.x;       // t = b*256 + mo
    int m = t & 255;
    float o[8];
    #pragma unroll
    for (int j = 0; j < 8; ++j) {
        float v = g_left[j * QP + t] + g_prod[j * QP + t];
        if (j == 0) v += b_left[m];
        o[j] = v * RSQRT2;
    }
    float4* op = reinterpret_cast<float4*>(out + (size_t)t * 8);
    op[0] = make_float4(o[0], o[1], o[2], o[3]);
    op[1] = make_float4(o[4], o[5], o[6], o[7]);
}

// ---------------- launch ----------------------------------------------------
extern "C" void kernel_launch(void* const* d_in, const int* in_sizes, int n_in,
                              void* d_out, int out_size)
{
    const float* x   = (const float*)d_in[0];
    const float* wr  = (const float*)d_in[1];
    const float* wl  = (const float*)d_in[2];
    const float* bl  = (const float*)d_in[3];
    const float* na  = (const float*)d_in[4];
    const float* gpw = (const float*)d_in[5];
    float* out = (float*)d_out;

    k_transpose_x<<<1024, 256>>>(x);
    k_prep_w<<<256, 256>>>(wr, wl);
    k_prep_gpw<<<256, 256>>>(gpw);

    // right + left linears in one launch: z in [0,16), z>>3 selects side
    k_sgemm8<<<dim3(2, 8, 16), 256>>>(0);

    k_build_U<<<1024, 256>>>(x, na);

    // grouped path GEMMs: grid.y = 8 + 24 + 24 + 8 = 64 block-rows
    k_sgemm_groups<<<dim3(2, 64), 256>>>();

    k_combine<<<1024, 256>>>(bl, out);
}

// round 4
// speedup vs baseline: 2.0038x; 1.8832x over previous
#include <cuda_runtime.h>
#include <cuda_bf16.h>
#include <math.h>
#include <stdint.h>

// ============================================================================
// FullyConnectedSteerableGeometricProductLayer — Cl(3,0)
// Tensor-core edition via portable mma.sync (sm_80-class HMMA, works on sm_103):
//   All GEMMs computed as split-bf16 with fp32 accumulation:
//     A*B ~= Ahi*Bhi + Ahi*Blo + Alo*Bhi   (K' = 3K, lo*lo dropped ~2^-18)
// 128x128 CTA tile, 8 warps (each 64x32 of m16n8k16), cp.async double buffer,
// ldmatrix fragment loads from SW128-swizzled smem.
// ============================================================================

#define QP (1024 * 256)
#define RSQRT2 0.70710678118654752440f

// ---------------- device scratch (static; no allocations) -------------------
__device__ float g_xr  [8 * QP];   // x_right raw planes  [comp][b][n]
__device__ float g_left[8 * QP];   // left linear planes  [comp][b][mo]
__device__ float g_prod[8 * QP];   // gp product planes   [comp][b][mo]

// split-bf16 operands (row cols [0,Khalf)=hi, [Khalf,2*Khalf)=lo)
__device__ __nv_bfloat16 g_xs [4194304];   // [comp][1024 b][512]
__device__ __nv_bfloat16 g_wrs[524288];    // [grade][256 n'][512]
__device__ __nv_bfloat16 g_wls[524288];    // [grade][256 mo][512]
__device__ __nv_bfloat16 g_wgs[2621440];   // per grade [256 mo][512*np]
__device__ __nv_bfloat16 g_Us [23068672];  // per grade [(jl,b)][512*np]

// ---------------- compile-time GA tables ------------------------------------
#define GA_TABLES \
  constexpr int   T_GR[8]     = {0,1,1,1,2,2,2,3};                       \
  constexpr int   T_RES[8][8] = {                                        \
    {0,1,2,3,4,5,6,7},{1,0,4,5,2,3,7,6},{2,4,0,6,1,7,3,5},               \
    {3,5,6,0,7,1,2,4},{4,2,1,7,0,6,5,3},{5,3,7,1,6,0,4,2},               \
    {6,7,3,2,5,4,0,1},{7,6,5,4,3,2,1,0}};                                \
  constexpr float T_SGN[8][8] = {                                        \
    { 1.f, 1.f, 1.f, 1.f, 1.f, 1.f, 1.f, 1.f},                           \
    { 1.f, 1.f, 1.f, 1.f, 1.f, 1.f, 1.f, 1.f},                           \
    { 1.f,-1.f, 1.f, 1.f,-1.f,-1.f, 1.f,-1.f},                           \
    { 1.f,-1.f,-1.f, 1.f, 1.f,-1.f,-1.f, 1.f},                           \
    { 1.f,-1.f, 1.f, 1.f,-1.f,-1.f, 1.f,-1.f},                           \
    { 1.f,-1.f,-1.f, 1.f, 1.f,-1.f,-1.f, 1.f},                           \
    { 1.f, 1.f,-1.f, 1.f,-1.f, 1.f,-1.f,-1.f},                           \
    { 1.f, 1.f,-1.f, 1.f,-1.f, 1.f,-1.f,-1.f}};                          \
  constexpr int   T_PLOC[4][4][4] = {                                    \
    { { 0,-1,-1,-1},{-1, 0,-1,-1},{-1,-1, 0,-1},{-1,-1,-1, 0} },         \
    { {-1, 1,-1,-1},{ 1,-1, 2,-1},{-1, 1,-1, 2},{-1,-1, 1,-1} },         \
    { {-1,-1, 2,-1},{-1, 3,-1, 4},{ 3,-1, 4,-1},{-1, 2,-1,-1} },         \
    { {-1,-1,-1, 3},{-1,-1, 5,-1},{-1, 5,-1,-1},{ 3,-1,-1,-1} } };       \
  constexpr int   T_NP[4]    = {4,6,6,4};                                \
  constexpr int   T_JLOC[8]  = {0,0,1,2,0,1,2,0};                        \
  constexpr int   T_JBASE[4] = {0,1,4,7};                                \
  constexpr long  T_UOFF2[4] = {0L, 2097152L, 11534336L, 20971520L};     \
  constexpr long  T_WOFF2[4] = {0L,  524288L,  1310720L,  2097152L};     \
  constexpr int   T_GLOBALP[4][6] = {                                    \
    {0,4,10,16,0,0},{1,5,6,11,12,17},{2,7,8,13,14,18},{3,9,15,19,0,0} };

// ---------------- PTX helpers ------------------------------------------------
__device__ __forceinline__ uint32_t smem_u32(const void* p) {
    uint32_t a;
    asm("{ .reg .u64 t; cvta.to.shared.u64 t, %1; cvt.u32.u64 %0, t; }"
        : "=r"(a) : "l"(p));
    return a;
}
__device__ __forceinline__ void cp16(uint32_t dst, const void* src) {
    asm volatile("cp.async.cg.shared.global [%0], [%1], 16;"
                 :: "r"(dst), "l"(src));
}
__device__ __forceinline__ void cp_commit() {
    asm volatile("cp.async.commit_group;" ::: "memory");
}
template<int N>
__device__ __forceinline__ void cp_wait() {
    asm volatile("cp.async.wait_group %0;" :: "n"(N) : "memory");
}
__device__ __forceinline__ void ldsm_x4(uint32_t& r0, uint32_t& r1,
                                        uint32_t& r2, uint32_t& r3, uint32_t a) {
    asm volatile("ldmatrix.sync.aligned.m8n8.x4.shared.b16 {%0,%1,%2,%3}, [%4];"
                 : "=r"(r0), "=r"(r1), "=r"(r2), "=r"(r3) : "r"(a));
}
__device__ __forceinline__ void ldsm_x2(uint32_t& r0, uint32_t& r1, uint32_t a) {
    asm volatile("ldmatrix.sync.aligned.m8n8.x2.shared.b16 {%0,%1}, [%2];"
                 : "=r"(r0), "=r"(r1) : "r"(a));
}
__device__ __forceinline__ void mma16816(float* c, uint32_t a0, uint32_t a1,
                                         uint32_t a2, uint32_t a3,
                                         uint32_t b0, uint32_t b1) {
    asm volatile("mma.sync.aligned.m16n8k16.row.col.f32.bf16.bf16.f32 "
                 "{%0,%1,%2,%3}, {%4,%5,%6,%7}, {%8,%9}, {%0,%1,%2,%3};"
                 : "+f"(c[0]), "+f"(c[1]), "+f"(c[2]), "+f"(c[3])
                 : "r"(a0), "r"(a1), "r"(a2), "r"(a3), "r"(b0), "r"(b1));
}

// ---------------- split helper ----------------------------------------------
__device__ __forceinline__ void bf16_split(float v, __nv_bfloat16& h, __nv_bfloat16& l) {
    h = __float2bfloat16(v);
    l = __float2bfloat16(v - __bfloat162float(h));
}

// ---------------- prep kernels ----------------------------------------------
__global__ void k_prep_x(const float* __restrict__ x)
{
    int t = blockIdx.x * 256 + threadIdx.x;   // t = b*256 + m
    int b = t >> 8, m = t & 255;
    const float4* xp = reinterpret_cast<const float4*>(x + (size_t)t * 8);
    float4 v0 = xp[0], v1 = xp[1];
    float xv[8] = {v0.x, v0.y, v0.z, v0.w, v1.x, v1.y, v1.z, v1.w};
    #pragma unroll
    for (int i = 0; i < 8; ++i) {
        __nv_bfloat16 h, l; bf16_split(xv[i], h, l);
        size_t base = (size_t)i * 524288 + (size_t)b * 512 + m;
        g_xs[base] = h; g_xs[base + 256] = l;
    }
}

__global__ void k_prep_w(const float* __restrict__ wr, const float* __restrict__ wl)
{
    int t = blockIdx.x * 256 + threadIdx.x;   // t = n*256 + m
    int n = t >> 8, m = t & 255;
    float4 a = reinterpret_cast<const float4*>(wr)[t];
    float4 c = reinterpret_cast<const float4*>(wl)[t];
    float av[4] = {a.x, a.y, a.z, a.w};
    float cv[4] = {c.x, c.y, c.z, c.w};
    #pragma unroll
    for (int g = 0; g < 4; ++g) {
        size_t base = (size_t)g * 131072 + (size_t)n * 512 + m;
        __nv_bfloat16 h, l;
        bf16_split(av[g], h, l); g_wrs[base] = h; g_wrs[base + 256] = l;
        bf16_split(cv[g], h, l); g_wls[base] = h; g_wls[base + 256] = l;
    }
}

__global__ void k_prep_gpw(const float* __restrict__ gpw)
{
    GA_TABLES
    int t  = blockIdx.x * 256 + threadIdx.x;  // t = mo*256 + n
    int mo = t >> 8, n = t & 255;
    float w[20];
    const float4* p4 = reinterpret_cast<const float4*>(gpw + (size_t)t * 20);
    #pragma unroll
    for (int q = 0; q < 5; ++q) {
        float4 v = p4[q];
        w[q*4+0] = v.x; w[q*4+1] = v.y; w[q*4+2] = v.z; w[q*4+3] = v.w;
    }
    #pragma unroll
    for (int g = 0; g < 4; ++g) {
        int np = T_NP[g];
        long base = T_WOFF2[g] + (long)mo * (512L * np) + (long)n * np;
        #pragma unroll
        for (int pl = 0; pl < 6; ++pl)
            if (pl < np) {
                __nv_bfloat16 h, l; bf16_split(w[T_GLOBALP[g][pl]], h, l);
                g_wgs[base + pl] = h; g_wgs[base + 256L * np + pl] = l;
            }
    }
}

// ---------------- HMMA mainloop ----------------------------------------------
// C(128x128) = A(128 x 3*Khalf) * B^T, 3 segments (hi,hi),(hi,lo),(lo,hi).
// A,B row-major bf16, ld = 2*Khalf elems. Chunk = 64 bf16 of K (128B rows).
// smem layout per buffer (32KB): A tile 16KB @0 (SW128), B tile 16KB @16384.

__device__ __forceinline__ void issue_chunk(
    const char* __restrict__ A, const char* __restrict__ B,
    int ld_bytes, int aoff_b, int boff_b, uint32_t dst, int tid)
{
    #pragma unroll
    for (int j = 0; j < 4; ++j) {
        int idx = tid + j * 256;
        int row = idx >> 3, c16 = idx & 7;
        uint32_t off = (uint32_t)(row * 128 + c16 * 16);
        off ^= (off >> 3) & 0x70;
        cp16(dst + off, A + (size_t)row * ld_bytes + aoff_b + c16 * 16);
    }
    #pragma unroll
    for (int j = 0; j < 4; ++j) {
        int idx = tid + j * 256;
        int row = idx >> 3, c16 = idx & 7;
        uint32_t off = (uint32_t)(row * 128 + c16 * 16);
        off ^= (off >> 3) & 0x70;
        cp16(dst + 16384 + off, B + (size_t)row * ld_bytes + boff_b + c16 * 16);
    }
}

__device__ __forceinline__ void compute_chunk(
    uint32_t smA, uint32_t smB, int lane, int wm, int wn, float acc[4][4][4])
{
    const uint32_t arow = (uint32_t)(wm * 64 + (lane & 15)) * 128;
    const uint32_t acol = ((lane >> 4) & 1) * 16;
    const uint32_t brow = (uint32_t)(wn * 32 + (lane & 7)) * 128;
    const uint32_t bcol = ((lane >> 3) & 1) * 16;
    #pragma unroll
    for (int ks = 0; ks < 4; ++ks) {
        uint32_t af[4][4];
        #pragma unroll
        for (int mt = 0; mt < 4; ++mt) {
            uint32_t off = arow + (uint32_t)(mt * 2048 + ks * 32) + acol;
            off ^= (off >> 3) & 0x70;
            ldsm_x4(af[mt][0], af[mt][1], af[mt][2], af[mt][3], smA + off);
        }
        #pragma unroll
        for (int nt = 0; nt < 4; ++nt) {
            uint32_t off = brow + (uint32_t)(nt * 1024 + ks * 32) + bcol;
            off ^= (off >> 3) & 0x70;
            uint32_t b0, b1;
            ldsm_x2(b0, b1, smB + off);
            #pragma unroll
            for (int mt = 0; mt < 4; ++mt)
                mma16816(acc[mt][nt], af[mt][0], af[mt][1], af[mt][2], af[mt][3], b0, b1);
        }
    }
}

__device__ __forceinline__ void mma_mainloop(
    const char* __restrict__ A, const char* __restrict__ B,
    int ld_bytes, int Khalf, uint32_t sm32, float acc[4][4][4])
{
    const int nk = Khalf >> 6;
    const int NC = 3 * nk;
    const int tid  = threadIdx.x;
    const int lane = tid & 31;
    const int wid  = tid >> 5;
    const int wm   = wid & 1;
    const int wn   = wid >> 1;

    #pragma unroll
    for (int mt = 0; mt < 4; ++mt)
        #pragma unroll
        for (int nt = 0; nt < 4; ++nt)
            #pragma unroll
            for (int q = 0; q < 4; ++q) acc[mt][nt][q] = 0.f;

    auto offs = [&](int c, int& ab, int& bb) {
        int seg = c / nk, cc = c - seg * nk;
        ab = ((seg == 2) ? Khalf * 2 : 0) + cc * 128;
        bb = ((seg == 1) ? Khalf * 2 : 0) + cc * 128;
    };

    int ab, bb;
    offs(0, ab, bb); issue_chunk(A, B, ld_bytes, ab, bb, sm32,          tid); cp_commit();
    offs(1, ab, bb); issue_chunk(A, B, ld_bytes, ab, bb, sm32 + 32768, tid); cp_commit();

    for (int c = 0; c < NC; ++c) {
        cp_wait<1>();
        __syncthreads();
        uint32_t base = sm32 + (uint32_t)(c & 1) * 32768;
        compute_chunk(base, base + 16384, lane, wm, wn, acc);
        __syncthreads();
        if (c + 2 < NC) {
            offs(c + 2, ab, bb);
            issue_chunk(A, B, ld_bytes, ab, bb, base, tid);
        }
        cp_commit();
    }
}

// ---------------- component linears (tensor) ---------------------------------
__global__ void __launch_bounds__(256, 2) k_lin()
{
    GA_TABLES
    extern __shared__ char dsm[];
    char* sm = reinterpret_cast<char*>(((uintptr_t)dsm + 1023) & ~(uintptr_t)1023);
    uint32_t sm32 = smem_u32(sm);

    int z = blockIdx.z & 7, which = blockIdx.z >> 3;
    const char* A = reinterpret_cast<const char*>(
        g_xs + (size_t)z * 524288 + (size_t)blockIdx.y * 128 * 512);
    const char* B = reinterpret_cast<const char*>(
        (which ? g_wls : g_wrs) + (size_t)T_GR[z] * 131072 + (size_t)blockIdx.x * 128 * 512);

    float acc[4][4][4];
    mma_mainloop(A, B, 1024, 256, sm32, acc);

    int lane = threadIdx.x & 31, wid = threadIdx.x >> 5;
    int wm = wid & 1, wn = wid >> 1;
    int g4 = lane >> 2, l2 = (lane & 3) * 2;
    float* C = (which ? g_left : g_xr) + (size_t)z * QP;
    int rbase = blockIdx.y * 128 + wm * 64;
    int cbase = blockIdx.x * 128 + wn * 32;
    #pragma unroll
    for (int mt = 0; mt < 4; ++mt)
        #pragma unroll
        for (int nt = 0; nt < 4; ++nt) {
            int r = rbase + mt * 16 + g4;
            int cc = cbase + nt * 8 + l2;
            *reinterpret_cast<float2*>(C + (size_t)r * 256 + cc) =
                make_float2(acc[mt][nt][0], acc[mt][nt][1]);
            *reinterpret_cast<float2*>(C + (size_t)(r + 8) * 256 + cc) =
                make_float2(acc[mt][nt][2], acc[mt][nt][3]);
        }
}

// ---------------- normalize + build grouped split-U --------------------------
__global__ void k_build_U(const float* __restrict__ x, const float* __restrict__ norm_a)
{
    GA_TABLES
    int t = blockIdx.x * 256 + threadIdx.x;   // t = b*256 + n
    int n = t & 255, b = t >> 8;

    float xv[8];
    {
        const float4* xp = reinterpret_cast<const float4*>(x + (size_t)t * 8);
        float4 v0 = xp[0], v1 = xp[1];
        xv[0]=v0.x; xv[1]=v0.y; xv[2]=v0.z; xv[3]=v0.w;
        xv[4]=v1.x; xv[5]=v1.y; xv[6]=v1.z; xv[7]=v1.w;
    }
    float xr[8];
    #pragma unroll
    for (int i = 0; i < 8; ++i) xr[i] = g_xr[i * QP + t];

    float ngr[4];
    ngr[0] = sqrtf(xr[0]*xr[0]);
    ngr[1] = sqrtf(xr[1]*xr[1] + xr[2]*xr[2] + xr[3]*xr[3]);
    ngr[2] = sqrtf(xr[4]*xr[4] + xr[5]*xr[5] + xr[6]*xr[6]);
    ngr[3] = sqrtf(xr[7]*xr[7]);
    float inv[4];
    #pragma unroll
    for (int g = 0; g < 4; ++g) {
        float a   = norm_a[n * 4 + g];
        float sig = 1.f / (1.f + expf(-a));
        inv[g] = 1.f / (sig * (ngr[g] - 1.f) + 1.f + 1e-6f);
    }
    #pragma unroll
    for (int i = 0; i < 8; ++i) xr[i] *= inv[T_GR[i]];

    float u[8][6];
    #pragma unroll
    for (int a = 0; a < 8; ++a)
        #pragma unroll
        for (int p = 0; p < 6; ++p) u[a][p] = 0.f;

    #pragma unroll
    for (int i = 0; i < 8; ++i) {
        #pragma unroll
        for (int k = 0; k < 8; ++k) {
            int jc = T_RES[i][k];
            int pl = T_PLOC[T_GR[i]][T_GR[jc]][T_GR[k]];
            u[jc][pl] += T_SGN[i][k] * xv[i] * xr[k];
        }
    }

    #pragma unroll
    for (int jc = 0; jc < 8; ++jc) {
        int g  = T_GR[jc];
        int np = T_NP[g];
        long base = T_UOFF2[g]
                  + (long)(T_JLOC[jc] * 1024 + b) * (512L * np)
                  + (long)n * np;
        #pragma unroll
        for (int p = 0; p < 6; ++p)
            if (p < np) {
                __nv_bfloat16 h, l; bf16_split(u[jc][p], h, l);
                g_Us[base + p] = h;
                g_Us[base + 256L * np + p] = l;
            }
    }
}

// ---------------- grouped path GEMMs (tensor) --------------------------------
__global__ void __launch_bounds__(256, 2) k_grp()
{
    GA_TABLES
    extern __shared__ char dsm[];
    char* sm = reinterpret_cast<char*>(((uintptr_t)dsm + 1023) & ~(uintptr_t)1023);
    uint32_t sm32 = smem_u32(sm);

    int y = blockIdx.y;
    int g, ly;
    if      (y <  8) { g = 0; ly = y;      }
    else if (y < 32) { g = 1; ly = y -  8; }
    else if (y < 56) { g = 2; ly = y - 32; }
    else             { g = 3; ly = y - 56; }
    int np = T_NP[g];
    int Khalf = 256 * np;
    size_t ld = 512 * (size_t)np;       // elems
    const char* A = reinterpret_cast<const char*>(
        g_Us + T_UOFF2[g] + (size_t)ly * 128 * ld);
    const char* B = reinterpret_cast<const char*>(
        g_wgs + T_WOFF2[g] + (size_t)blockIdx.x * 128 * ld);

    float acc[4][4][4];
    mma_mainloop(A, B, (int)(ld * 2), Khalf, sm32, acc);

    int lane = threadIdx.x & 31, wid = threadIdx.x >> 5;
    int wm = wid & 1, wn = wid >> 1;
    int g4 = lane >> 2, l2 = (lane & 3) * 2;
    int rbase = ly * 128 + wm * 64;
    int cbase = blockIdx.x * 128 + wn * 32;
    #pragma unroll
    for (int mt = 0; mt < 4; ++mt)
        #pragma unroll
        for (int nt = 0; nt < 4; ++nt) {
            int r0 = rbase + mt * 16 + g4;
            int cc = cbase + nt * 8 + l2;
            #pragma unroll
            for (int hh = 0; hh < 2; ++hh) {
                int r  = r0 + hh * 8;
                int jc = T_JBASE[g] + (r >> 10);
                int bb = r & 1023;
                *reinterpret_cast<float2*>(
                    g_prod + (size_t)jc * QP + (size_t)bb * 256 + cc) =
                    make_float2(acc[mt][nt][hh * 2], acc[mt][nt][hh * 2 + 1]);
            }
        }
}

// ---------------- final combine ----------------------------------------------
__global__ void k_combine(const float* __restrict__ b_left, float* __restrict__ out)
{
    int t = blockIdx.x * 256 + threadIdx.x;   // t = b*256 + mo
    int m = t & 255;
    float o[8];
    #pragma unroll
    for (int j = 0; j < 8; ++j) {
        float v = g_left[j * QP + t] + g_prod[j * QP + t];
        if (j == 0) v += b_left[m];
        o[j] = v * RSQRT2;
    }
    float4* op = reinterpret_cast<float4*>(out + (size_t)t * 8);
    op[0] = make_float4(o[0], o[1], o[2], o[3]);
    op[1] = make_float4(o[4], o[5], o[6], o[7]);
}

// ---------------- launch -----------------------------------------------------
#define DSMEM_BYTES (65536 + 1024)

extern "C" void kernel_launch(void* const* d_in, const int* in_sizes, int n_in,
                              void* d_out, int out_size)
{
    const float* x   = (const float*)d_in[0];
    const float* wr  = (const float*)d_in[1];
    const float* wl  = (const float*)d_in[2];
    const float* bl  = (const float*)d_in[3];
    const float* na  = (const float*)d_in[4];
    const float* gpw = (const float*)d_in[5];
    float* out = (float*)d_out;

    cudaFuncSetAttribute(k_lin, cudaFuncAttributeMaxDynamicSharedMemorySize, DSMEM_BYTES);
    cudaFuncSetAttribute(k_grp, cudaFuncAttributeMaxDynamicSharedMemorySize, DSMEM_BYTES);

    k_prep_x  <<<1024, 256>>>(x);
    k_prep_w  <<<256, 256>>>(wr, wl);
    k_prep_gpw<<<256, 256>>>(gpw);

    // right + left linears: z in [0,16), z>>3 selects side
    k_lin<<<dim3(2, 8, 16), 256, DSMEM_BYTES>>>();

    k_build_U<<<1024, 256>>>(x, na);

    // grouped GEMMs: grid.y = 8 + 24 + 24 + 8 = 64 block-rows
    k_grp<<<dim3(2, 64), 256, DSMEM_BYTES>>>();

    k_combine<<<1024, 256>>>(bl, out);
}

// round 5
// speedup vs baseline: 2.1704x; 1.0831x over previous
#include <cuda_runtime.h>
#include <cuda_bf16.h>
#include <math.h>
#include <stdint.h>

// ============================================================================
// FullyConnectedSteerableGeometricProductLayer — Cl(3,0)
// mma.sync bf16 split (hi/lo) GEMMs, fp32 accum:
//   A*B ~= Ahi*Bhi + Ahi*Blo + Alo*Bhi   (K' = 3K)
// R5: 3-stage cp.async pipeline (1 sync/chunk), fused grp+left launch,
//     ldmatrix.x4 B-fragments, merged prep.
// ============================================================================

#define QP (1024 * 256)
#define RSQRT2 0.70710678118654752440f

// ---------------- device scratch (static; no allocations) -------------------
__device__ float g_xr  [8 * QP];
__device__ float g_left[8 * QP];
__device__ float g_prod[8 * QP];

__device__ __nv_bfloat16 g_xs [4194304];   // [comp][1024 b][512]
__device__ __nv_bfloat16 g_wrs[524288];    // [grade][256 n'][512]
__device__ __nv_bfloat16 g_wls[524288];    // [grade][256 mo][512]
__device__ __nv_bfloat16 g_wgs[2621440];   // per grade [256 mo][512*np]
__device__ __nv_bfloat16 g_Us [23068672];  // per grade [(jl,b)][512*np]

// ---------------- compile-time GA tables ------------------------------------
#define GA_TABLES \
  constexpr int   T_GR[8]     = {0,1,1,1,2,2,2,3};                       \
  constexpr int   T_RES[8][8] = {                                        \
    {0,1,2,3,4,5,6,7},{1,0,4,5,2,3,7,6},{2,4,0,6,1,7,3,5},               \
    {3,5,6,0,7,1,2,4},{4,2,1,7,0,6,5,3},{5,3,7,1,6,0,4,2},               \
    {6,7,3,2,5,4,0,1},{7,6,5,4,3,2,1,0}};                                \
  constexpr float T_SGN[8][8] = {                                        \
    { 1.f, 1.f, 1.f, 1.f, 1.f, 1.f, 1.f, 1.f},                           \
    { 1.f, 1.f, 1.f, 1.f, 1.f, 1.f, 1.f, 1.f},                           \
    { 1.f,-1.f, 1.f, 1.f,-1.f,-1.f, 1.f,-1.f},                           \
    { 1.f,-1.f,-1.f, 1.f, 1.f,-1.f,-1.f, 1.f},                           \
    { 1.f,-1.f, 1.f, 1.f,-1.f,-1.f, 1.f,-1.f},                           \
    { 1.f,-1.f,-1.f, 1.f, 1.f,-1.f,-1.f, 1.f},                           \
    { 1.f, 1.f,-1.f, 1.f,-1.f, 1.f,-1.f,-1.f},                           \
    { 1.f, 1.f,-1.f, 1.f,-1.f, 1.f,-1.f,-1.f}};                          \
  constexpr int   T_PLOC[4][4][4] = {                                    \
    { { 0,-1,-1,-1},{-1, 0,-1,-1},{-1,-1, 0,-1},{-1,-1,-1, 0} },         \
    { {-1, 1,-1,-1},{ 1,-1, 2,-1},{-1, 1,-1, 2},{-1,-1, 1,-1} },         \
    { {-1,-1, 2,-1},{-1, 3,-1, 4},{ 3,-1, 4,-1},{-1, 2,-1,-1} },         \
    { {-1,-1,-1, 3},{-1,-1, 5,-1},{-1, 5,-1,-1},{ 3,-1,-1,-1} } };       \
  constexpr int   T_NP[4]    = {4,6,6,4};                                \
  constexpr int   T_JLOC[8]  = {0,0,1,2,0,1,2,0};                        \
  constexpr int   T_JBASE[4] = {0,1,4,7};                                \
  constexpr long  T_UOFF2[4] = {0L, 2097152L, 11534336L, 20971520L};     \
  constexpr long  T_WOFF2[4] = {0L,  524288L,  1310720L,  2097152L};     \
  constexpr int   T_GLOBALP[4][6] = {                                    \
    {0,4,10,16,0,0},{1,5,6,11,12,17},{2,7,8,13,14,18},{3,9,15,19,0,0} };

// ---------------- PTX helpers ------------------------------------------------
__device__ __forceinline__ uint32_t smem_u32(const void* p) {
    uint32_t a;
    asm("{ .reg .u64 t; cvta.to.shared.u64 t, %1; cvt.u32.u64 %0, t; }"
        : "=r"(a) : "l"(p));
    return a;
}
__device__ __forceinline__ void cp16(uint32_t dst, const void* src) {
    asm volatile("cp.async.cg.shared.global [%0], [%1], 16;"
                 :: "r"(dst), "l"(src));
}
__device__ __forceinline__ void cp_commit() {
    asm volatile("cp.async.commit_group;" ::: "memory");
}
template<int N>
__device__ __forceinline__ void cp_wait() {
    asm volatile("cp.async.wait_group %0;" :: "n"(N) : "memory");
}
__device__ __forceinline__ void ldsm_x4(uint32_t& r0, uint32_t& r1,
                                        uint32_t& r2, uint32_t& r3, uint32_t a) {
    asm volatile("ldmatrix.sync.aligned.m8n8.x4.shared.b16 {%0,%1,%2,%3}, [%4];"
                 : "=r"(r0), "=r"(r1), "=r"(r2), "=r"(r3) : "r"(a));
}
__device__ __forceinline__ void mma16816(float* c, uint32_t a0, uint32_t a1,
                                         uint32_t a2, uint32_t a3,
                                         uint32_t b0, uint32_t b1) {
    asm volatile("mma.sync.aligned.m16n8k16.row.col.f32.bf16.bf16.f32 "
                 "{%0,%1,%2,%3}, {%4,%5,%6,%7}, {%8,%9}, {%0,%1,%2,%3};"
                 : "+f"(c[0]), "+f"(c[1]), "+f"(c[2]), "+f"(c[3])
                 : "r"(a0), "r"(a1), "r"(a2), "r"(a3), "r"(b0), "r"(b1));
}

__device__ __forceinline__ void bf16_split(float v, __nv_bfloat16& h, __nv_bfloat16& l) {
    h = __float2bfloat16(v);
    l = __float2bfloat16(v - __bfloat162float(h));
}

// ---------------- merged prep kernel -----------------------------------------
__global__ void k_prep(const float* __restrict__ x, const float* __restrict__ wr,
                       const float* __restrict__ wl, const float* __restrict__ gpw)
{
    GA_TABLES
    int blk = blockIdx.x;
    if (blk < 1024) {                                   // ---- x split
        int t = blk * 256 + threadIdx.x;                // t = b*256 + m
        int b = t >> 8, m = t & 255;
        const float4* xp = reinterpret_cast<const float4*>(x + (size_t)t * 8);
        float4 v0 = xp[0], v1 = xp[1];
        float xv[8] = {v0.x, v0.y, v0.z, v0.w, v1.x, v1.y, v1.z, v1.w};
        #pragma unroll
        for (int i = 0; i < 8; ++i) {
            __nv_bfloat16 h, l; bf16_split(xv[i], h, l);
            size_t base = (size_t)i * 524288 + (size_t)b * 512 + m;
            g_xs[base] = h; g_xs[base + 256] = l;
        }
    } else if (blk < 1280) {                            // ---- w_right / w_left
        int t = (blk - 1024) * 256 + threadIdx.x;       // t = n*256 + m
        int n = t >> 8, m = t & 255;
        float4 a = reinterpret_cast<const float4*>(wr)[t];
        float4 c = reinterpret_cast<const float4*>(wl)[t];
        float av[4] = {a.x, a.y, a.z, a.w};
        float cv[4] = {c.x, c.y, c.z, c.w};
        #pragma unroll
        for (int g = 0; g < 4; ++g) {
            size_t base = (size_t)g * 131072 + (size_t)n * 512 + m;
            __nv_bfloat16 h, l;
            bf16_split(av[g], h, l); g_wrs[base] = h; g_wrs[base + 256] = l;
            bf16_split(cv[g], h, l); g_wls[base] = h; g_wls[base + 256] = l;
        }
    } else {                                            // ---- gp weights
        int t  = (blk - 1280) * 256 + threadIdx.x;      // t = mo*256 + n
        int mo = t >> 8, n = t & 255;
        float w[20];
        const float4* p4 = reinterpret_cast<const float4*>(gpw + (size_t)t * 20);
        #pragma unroll
        for (int q = 0; q < 5; ++q) {
            float4 v = p4[q];
            w[q*4+0] = v.x; w[q*4+1] = v.y; w[q*4+2] = v.z; w[q*4+3] = v.w;
        }
        #pragma unroll
        for (int g = 0; g < 4; ++g) {
            int np = T_NP[g];
            long base = T_WOFF2[g] + (long)mo * (512L * np) + (long)n * np;
            #pragma unroll
            for (int pl = 0; pl < 6; ++pl)
                if (pl < np) {
                    __nv_bfloat16 h, l; bf16_split(w[T_GLOBALP[g][pl]], h, l);
                    g_wgs[base + pl] = h; g_wgs[base + 256L * np + pl] = l;
                }
        }
    }
}

// ---------------- HMMA mainloop (3-stage cp.async) ---------------------------
// C(128x128) = A(128 x 3*Khalf) * B^T, segments (hi,hi),(hi,lo),(lo,hi).
// Chunk = 64 bf16 of K (128B rows, SW128). Stage = 32KB (A 16KB + B 16KB).
#define STG 32768

__device__ __forceinline__ void issue_chunk(
    const char* __restrict__ A, const char* __restrict__ B,
    int ld_bytes, int aoff_b, int boff_b, uint32_t dst, int tid)
{
    #pragma unroll
    for (int j = 0; j < 4; ++j) {
        int idx = tid + j * 256;
        int row = idx >> 3, c16 = idx & 7;
        uint32_t off = (uint32_t)(row * 128 + c16 * 16);
        off ^= (off >> 3) & 0x70;
        cp16(dst + off, A + (size_t)row * ld_bytes + aoff_b + c16 * 16);
    }
    #pragma unroll
    for (int j = 0; j < 4; ++j) {
        int idx = tid + j * 256;
        int row = idx >> 3, c16 = idx & 7;
        uint32_t off = (uint32_t)(row * 128 + c16 * 16);
        off ^= (off >> 3) & 0x70;
        cp16(dst + 16384 + off, B + (size_t)row * ld_bytes + boff_b + c16 * 16);
    }
}

__device__ __forceinline__ void compute_chunk(
    uint32_t smA, uint32_t smB, int lane, int wm, int wn, float acc[4][4][4])
{
    const uint32_t arow = (uint32_t)(wm * 64 + (lane & 15)) * 128;
    const uint32_t acol = ((lane >> 4) & 1) * 16;
    // B x4 addressing: lane -> matrix m = lane>>3, row r = lane&7
    const int bm = lane >> 3, br = lane & 7;
    const uint32_t brow = (uint32_t)(wn * 32 + (bm >> 1) * 8 + br) * 128;
    const uint32_t bcol = (uint32_t)(bm & 1) * 16;
    #pragma unroll
    for (int ks = 0; ks < 4; ++ks) {
        uint32_t af[4][4];
        #pragma unroll
        for (int mt = 0; mt < 4; ++mt) {
            uint32_t off = arow + (uint32_t)(mt * 2048 + ks * 32) + acol;
            off ^= (off >> 3) & 0x70;
            ldsm_x4(af[mt][0], af[mt][1], af[mt][2], af[mt][3], smA + off);
        }
        uint32_t bf[4][2];
        #pragma unroll
        for (int p2 = 0; p2 < 2; ++p2) {   // nt pairs {0,1}, {2,3}
            uint32_t off = brow + (uint32_t)(p2 * 2048 + ks * 32) + bcol;
            off ^= (off >> 3) & 0x70;
            ldsm_x4(bf[p2*2][0], bf[p2*2][1], bf[p2*2+1][0], bf[p2*2+1][1], smB + off);
        }
        #pragma unroll
        for (int nt = 0; nt < 4; ++nt)
            #pragma unroll
            for (int mt = 0; mt < 4; ++mt)
                mma16816(acc[mt][nt], af[mt][0], af[mt][1], af[mt][2], af[mt][3],
                         bf[nt][0], bf[nt][1]);
    }
}

__device__ __forceinline__ void mma_mainloop(
    const char* __restrict__ A, const char* __restrict__ B,
    int ld_bytes, int Khalf, uint32_t sm32, float acc[4][4][4])
{
    const int nk = Khalf >> 6;
    const int NC = 3 * nk;
    const int tid  = threadIdx.x;
    const int lane = tid & 31;
    const int wid  = tid >> 5;
    const int wm   = wid & 1;
    const int wn   = wid >> 1;

    #pragma unroll
    for (int mt = 0; mt < 4; ++mt)
        #pragma unroll
        for (int nt = 0; nt < 4; ++nt)
            #pragma unroll
            for (int q = 0; q < 4; ++q) acc[mt][nt][q] = 0.f;

    auto offs = [&](int c, int& ab, int& bb) {
        int seg = c / nk, cc = c - seg * nk;
        ab = ((seg == 2) ? Khalf * 2 : 0) + cc * 128;
        bb = ((seg == 1) ? Khalf * 2 : 0) + cc * 128;
    };

    int ab, bb;
    offs(0, ab, bb); issue_chunk(A, B, ld_bytes, ab, bb, sm32,       tid); cp_commit();
    offs(1, ab, bb); issue_chunk(A, B, ld_bytes, ab, bb, sm32 + STG, tid); cp_commit();

    int s_cur = 0, s_nxt = 2;   // stage indices mod 3
    for (int c = 0; c < NC; ++c) {
        cp_wait<1>();
        __syncthreads();
        if (c + 2 < NC) {
            offs(c + 2, ab, bb);
            issue_chunk(A, B, ld_bytes, ab, bb, sm32 + (uint32_t)s_nxt * STG, tid);
        }
        cp_commit();
        uint32_t base = sm32 + (uint32_t)s_cur * STG;
        compute_chunk(base, base + 16384, lane, wm, wn, acc);
        s_cur = (s_cur == 2) ? 0 : s_cur + 1;
        s_nxt = (s_nxt == 2) ? 0 : s_nxt + 1;
    }
}

// ---------------- epilogue helper --------------------------------------------
struct EpiCoord { int lane, wm, wn, g4, l2; };
__device__ __forceinline__ EpiCoord epi_coord() {
    EpiCoord e;
    e.lane = threadIdx.x & 31;
    int wid = threadIdx.x >> 5;
    e.wm = wid & 1; e.wn = wid >> 1;
    e.g4 = e.lane >> 2; e.l2 = (e.lane & 3) * 2;
    return e;
}

// ---------------- phase 1: right linears -------------------------------------
__global__ void __launch_bounds__(256, 2) k_lin_r()
{
    GA_TABLES
    extern __shared__ char dsm[];
    char* sm = reinterpret_cast<char*>(((uintptr_t)dsm + 1023) & ~(uintptr_t)1023);
    uint32_t sm32 = smem_u32(sm);

    int z = blockIdx.z;
    const char* A = reinterpret_cast<const char*>(
        g_xs + (size_t)z * 524288 + (size_t)blockIdx.y * 128 * 512);
    const char* B = reinterpret_cast<const char*>(
        g_wrs + (size_t)T_GR[z] * 131072 + (size_t)blockIdx.x * 128 * 512);

    float acc[4][4][4];
    mma_mainloop(A, B, 1024, 256, sm32, acc);

    EpiCoord e = epi_coord();
    float* C = g_xr + (size_t)z * QP;
    int rbase = blockIdx.y * 128 + e.wm * 64;
    int cbase = blockIdx.x * 128 + e.wn * 32;
    #pragma unroll
    for (int mt = 0; mt < 4; ++mt)
        #pragma unroll
        for (int nt = 0; nt < 4; ++nt) {
            int r = rbase + mt * 16 + e.g4;
            int cc = cbase + nt * 8 + e.l2;
            *reinterpret_cast<float2*>(C + (size_t)r * 256 + cc) =
                make_float2(acc[mt][nt][0], acc[mt][nt][1]);
            *reinterpret_cast<float2*>(C + (size_t)(r + 8) * 256 + cc) =
                make_float2(acc[mt][nt][2], acc[mt][nt][3]);
        }
}

// ---------------- normalize + build grouped split-U --------------------------
__global__ void k_build_U(const float* __restrict__ x, const float* __restrict__ norm_a)
{
    GA_TABLES
    int t = blockIdx.x * 256 + threadIdx.x;   // t = b*256 + n
    int n = t & 255, b = t >> 8;

    float xv[8];
    {
        const float4* xp = reinterpret_cast<const float4*>(x + (size_t)t * 8);
        float4 v0 = xp[0], v1 = xp[1];
        xv[0]=v0.x; xv[1]=v0.y; xv[2]=v0.z; xv[3]=v0.w;
        xv[4]=v1.x; xv[5]=v1.y; xv[6]=v1.z; xv[7]=v1.w;
    }
    float xr[8];
    #pragma unroll
    for (int i = 0; i < 8; ++i) xr[i] = g_xr[i * QP + t];

    float ngr[4];
    ngr[0] = sqrtf(xr[0]*xr[0]);
    ngr[1] = sqrtf(xr[1]*xr[1] + xr[2]*xr[2] + xr[3]*xr[3]);
    ngr[2] = sqrtf(xr[4]*xr[4] + xr[5]*xr[5] + xr[6]*xr[6]);
    ngr[3] = sqrtf(xr[7]*xr[7]);
    float inv[4];
    #pragma unroll
    for (int g = 0; g < 4; ++g) {
        float a   = norm_a[n * 4 + g];
        float sig = 1.f / (1.f + expf(-a));
        inv[g] = 1.f / (sig * (ngr[g] - 1.f) + 1.f + 1e-6f);
    }
    #pragma unroll
    for (int i = 0; i < 8; ++i) xr[i] *= inv[T_GR[i]];

    float u[8][6];
    #pragma unroll
    for (int a = 0; a < 8; ++a)
        #pragma unroll
        for (int p = 0; p < 6; ++p) u[a][p] = 0.f;

    #pragma unroll
    for (int i = 0; i < 8; ++i) {
        #pragma unroll
        for (int k = 0; k < 8; ++k) {
            int jc = T_RES[i][k];
            int pl = T_PLOC[T_GR[i]][T_GR[jc]][T_GR[k]];
            u[jc][pl] += T_SGN[i][k] * xv[i] * xr[k];
        }
    }

    #pragma unroll
    for (int jc = 0; jc < 8; ++jc) {
        int g  = T_GR[jc];
        int np = T_NP[g];
        long base = T_UOFF2[g]
                  + (long)(T_JLOC[jc] * 1024 + b) * (512L * np)
                  + (long)n * np;
        #pragma unroll
        for (int p = 0; p < 6; ++p)
            if (p < np) {
                __nv_bfloat16 h, l; bf16_split(u[jc][p], h, l);
                g_Us[base + p] = h;
                g_Us[base + 256L * np + p] = l;
            }
    }
}

// ---------------- phase 2: grouped GEMMs + left linears (fused) --------------
__global__ void __launch_bounds__(256, 2) k_fused()
{
    GA_TABLES
    extern __shared__ char dsm[];
    char* sm = reinterpret_cast<char*>(((uintptr_t)dsm + 1023) & ~(uintptr_t)1023);
    uint32_t sm32 = smem_u32(sm);

    int y = blockIdx.y;
    float acc[4][4][4];
    EpiCoord e = epi_coord();
    int cbase = blockIdx.x * 128 + e.wn * 32;

    if (y < 64) {                       // ---- grouped path GEMM tile
        int g, ly;
        if      (y <  8) { g = 0; ly = y;      }
        else if (y < 32) { g = 1; ly = y -  8; }
        else if (y < 56) { g = 2; ly = y - 32; }
        else             { g = 3; ly = y - 56; }
        int np = T_NP[g];
        int Khalf = 256 * np;
        size_t ld = 512 * (size_t)np;
        const char* A = reinterpret_cast<const char*>(
            g_Us + T_UOFF2[g] + (size_t)ly * 128 * ld);
        const char* B = reinterpret_cast<const char*>(
            g_wgs + T_WOFF2[g] + (size_t)blockIdx.x * 128 * ld);
        mma_mainloop(A, B, (int)(ld * 2), Khalf, sm32, acc);

        int rbase = ly * 128 + e.wm * 64;
        #pragma unroll
        for (int mt = 0; mt < 4; ++mt)
            #pragma unroll
            for (int nt = 0; nt < 4; ++nt) {
                int r0 = rbase + mt * 16 + e.g4;
                int cc = cbase + nt * 8 + e.l2;
                #pragma unroll
                for (int hh = 0; hh < 2; ++hh) {
                    int r  = r0 + hh * 8;
                    int jc = T_JBASE[g] + (r >> 10);
                    int bb = r & 1023;
                    *reinterpret_cast<float2*>(
                        g_prod + (size_t)jc * QP + (size_t)bb * 256 + cc) =
                        make_float2(acc[mt][nt][hh * 2], acc[mt][nt][hh * 2 + 1]);
                }
            }
    } else {                            // ---- left linear tile
        int t = y - 64;
        int z = t >> 3, rowblk = t & 7;
        const char* A = reinterpret_cast<const char*>(
            g_xs + (size_t)z * 524288 + (size_t)rowblk * 128 * 512);
        const char* B = reinterpret_cast<const char*>(
            g_wls + (size_t)T_GR[z] * 131072 + (size_t)blockIdx.x * 128 * 512);
        mma_mainloop(A, B, 1024, 256, sm32, acc);

        float* C = g_left + (size_t)z * QP;
        int rbase = rowblk * 128 + e.wm * 64;
        #pragma unroll
        for (int mt = 0; mt < 4; ++mt)
            #pragma unroll
            for (int nt = 0; nt < 4; ++nt) {
                int r = rbase + mt * 16 + e.g4;
                int cc = cbase + nt * 8 + e.l2;
                *reinterpret_cast<float2*>(C + (size_t)r * 256 + cc) =
                    make_float2(acc[mt][nt][0], acc[mt][nt][1]);
                *reinterpret_cast<float2*>(C + (size_t)(r + 8) * 256 + cc) =
                    make_float2(acc[mt][nt][2], acc[mt][nt][3]);
            }
    }
}

// ---------------- final combine ----------------------------------------------
__global__ void k_combine(const float* __restrict__ b_left, float* __restrict__ out)
{
    int t = blockIdx.x * 256 + threadIdx.x;   // t = b*256 + mo
    int m = t & 255;
    float o[8];
    #pragma unroll
    for (int j = 0; j < 8; ++j) {
        float v = g_left[j * QP + t] + g_prod[j * QP + t];
        if (j == 0) v += b_left[m];
        o[j] = v * RSQRT2;
    }
    float4* op = reinterpret_cast<float4*>(out + (size_t)t * 8);
    op[0] = make_float4(o[0], o[1], o[2], o[3]);
    op[1] = make_float4(o[4], o[5], o[6], o[7]);
}

// ---------------- launch -----------------------------------------------------
#define DSMEM_BYTES (3 * 32768 + 1024)

extern "C" void kernel_launch(void* const* d_in, const int* in_sizes, int n_in,
                              void* d_out, int out_size)
{
    const float* x   = (const float*)d_in[0];
    const float* wr  = (const float*)d_in[1];
    const float* wl  = (const float*)d_in[2];
    const float* bl  = (const float*)d_in[3];
    const float* na  = (const float*)d_in[4];
    const float* gpw = (const float*)d_in[5];
    float* out = (float*)d_out;

    cudaFuncSetAttribute(k_lin_r, cudaFuncAttributeMaxDynamicSharedMemorySize, DSMEM_BYTES);
    cudaFuncSetAttribute(k_fused, cudaFuncAttributeMaxDynamicSharedMemorySize, DSMEM_BYTES);

    k_prep<<<1536, 256>>>(x, wr, wl, gpw);

    k_lin_r<<<dim3(2, 8, 8), 256, DSMEM_BYTES>>>();

    k_build_U<<<1024, 256>>>(x, na);

    // y: 64 grouped row-tiles + 64 left-linear tiles
    k_fused<<<dim3(2, 128), 256, DSMEM_BYTES>>>();

    k_combine<<<1024, 256>>>(bl, out);
}